// round 3
// baseline (speedup 1.0000x reference)
#include <cuda_runtime.h>

// ---------------------------------------------------------------------------
// ClassifierHetero: only the live dataflow of the reference is implemented.
// The HeteroGraphConv layers are dead code in the reference (outputs deleted,
// never written back to the graph). Live computation:
//   hg[b] = [mean(h_comp|g=b), mean2(h_port|g=b), mean(h_net|g=b)]  -> [64,4]
//   out   = relu(relu(hg@Wc1+bc1)@Wc2+bc2)@Wc3+bc3                  -> [64,10]
// ---------------------------------------------------------------------------

#define NB 64  // number of graphs (B)

// Scratch (allocation-free: __device__ globals).
// g_sum layout: [0]=comp, [1]=port col0, [2]=port col1, [3]=net ; each NB wide.
// g_cnt layout: [0]=comp, [1]=port, [2]=net ; each NB wide.
__device__ float g_sum[4 * NB];
__device__ int   g_cnt[3 * NB];

__global__ void hx_init_kernel() {
    int t = threadIdx.x;
    if (t < 4 * NB) g_sum[t] = 0.0f;
    if (t < 3 * NB) g_cnt[t] = 0;
}

__global__ void hx_reduce_kernel(const float* __restrict__ h_comp,
                                 const int*   __restrict__ gid_comp, int nc,
                                 const float* __restrict__ h_port,
                                 const int*   __restrict__ gid_port, int np,
                                 const float* __restrict__ h_net,
                                 const int*   __restrict__ gid_net,  int nn) {
    __shared__ float s_sum[4 * NB];
    __shared__ int   s_cnt[3 * NB];
    for (int i = threadIdx.x; i < 4 * NB; i += blockDim.x) s_sum[i] = 0.0f;
    for (int i = threadIdx.x; i < 3 * NB; i += blockDim.x) s_cnt[i] = 0;
    __syncthreads();

    long long total = (long long)nc + (long long)np + (long long)nn;
    long long chunk = (total + gridDim.x - 1) / gridDim.x;
    long long start = (long long)blockIdx.x * chunk;
    long long stop  = start + chunk;
    if (stop > total) stop = total;

    for (long long i = start + threadIdx.x; i < stop; i += blockDim.x) {
        if (i < nc) {
            int idx = (int)i;
            int g = gid_comp[idx];
            atomicAdd(&s_sum[0 * NB + g], h_comp[idx]);
            atomicAdd(&s_cnt[0 * NB + g], 1);
        } else if (i < (long long)nc + np) {
            int idx = (int)(i - nc);
            int g = gid_port[idx];
            float2 v = reinterpret_cast<const float2*>(h_port)[idx];
            atomicAdd(&s_sum[1 * NB + g], v.x);
            atomicAdd(&s_sum[2 * NB + g], v.y);
            atomicAdd(&s_cnt[1 * NB + g], 1);
        } else {
            int idx = (int)(i - nc - np);
            int g = gid_net[idx];
            atomicAdd(&s_sum[3 * NB + g], h_net[idx]);
            atomicAdd(&s_cnt[2 * NB + g], 1);
        }
    }
    __syncthreads();

    // gids are sorted -> each block touches very few bins; flush nonzeros only.
    // (Skipping exact-0.0 sums is value-safe: adding 0 is a no-op.)
    for (int i = threadIdx.x; i < 4 * NB; i += blockDim.x)
        if (s_sum[i] != 0.0f) atomicAdd(&g_sum[i], s_sum[i]);
    for (int i = threadIdx.x; i < 3 * NB; i += blockDim.x)
        if (s_cnt[i] != 0) atomicAdd(&g_cnt[i], s_cnt[i]);
}

// One block per graph row b (64 blocks x 128 threads).
__global__ void hx_mlp_kernel(const float* __restrict__ Wc1, const float* __restrict__ bc1,
                              const float* __restrict__ Wc2, const float* __restrict__ bc2,
                              const float* __restrict__ Wc3, const float* __restrict__ bc3,
                              float* __restrict__ out) {
    const int b = blockIdx.x;
    const int j = threadIdx.x;  // 0..127

    __shared__ float shg[4];
    __shared__ float sh1[128];
    __shared__ float sh2[128];

    if (j < 4) {
        float s = g_sum[j * NB + b];
        int ci = (j == 0) ? 0 : (j == 3) ? 2 : 1;  // comp / port / net counter
        float c = (float)g_cnt[ci * NB + b];
        shg[j] = s / fmaxf(c, 1.0f);
    }
    __syncthreads();

    const float hg0 = shg[0], hg1 = shg[1], hg2 = shg[2], hg3 = shg[3];

    float v = hg0 * Wc1[0 * 128 + j] + hg1 * Wc1[1 * 128 + j] +
              hg2 * Wc1[2 * 128 + j] + hg3 * Wc1[3 * 128 + j] + bc1[j];
    sh1[j] = fmaxf(v, 0.0f);
    __syncthreads();

    float acc = bc2[j];
#pragma unroll 8
    for (int k = 0; k < 128; k++) acc = fmaf(sh1[k], Wc2[k * 128 + j], acc);
    sh2[j] = fmaxf(acc, 0.0f);
    __syncthreads();

    if (j < 10) {
        float o = bc3[j];
#pragma unroll 8
        for (int k = 0; k < 128; k++) o = fmaf(sh2[k], Wc3[k * 10 + j], o);
        out[b * 10 + j] = o;
    }
}

extern "C" void kernel_launch(void* const* d_in, const int* in_sizes, int n_in,
                              void* d_out, int out_size) {
    // metadata order (reference signature order):
    //  0 h_comp [NC,1]   1 h_port [NP,2]   2 h_net [NN,1]
    //  3..6 edge index arrays (dead)
    //  7 gid_comp        8 gid_port        9 gid_net
    // 10..21 conv weights/biases (dead)
    // 22 Wc1  23 bc1  24 Wc2  25 bc2  26 Wc3  27 bc3
    const float* h_comp  = (const float*)d_in[0];
    const float* h_port  = (const float*)d_in[1];
    const float* h_net   = (const float*)d_in[2];
    const int* gid_comp  = (const int*)d_in[7];
    const int* gid_port  = (const int*)d_in[8];
    const int* gid_net   = (const int*)d_in[9];
    const float* Wc1 = (const float*)d_in[22];
    const float* bc1 = (const float*)d_in[23];
    const float* Wc2 = (const float*)d_in[24];
    const float* bc2 = (const float*)d_in[25];
    const float* Wc3 = (const float*)d_in[26];
    const float* bc3 = (const float*)d_in[27];
    float* out = (float*)d_out;

    const int nc = in_sizes[0];
    const int np = in_sizes[1] / 2;
    const int nn = in_sizes[2];

    hx_init_kernel<<<1, 256>>>();
    hx_reduce_kernel<<<592, 256>>>(h_comp, gid_comp, nc,
                                   h_port, gid_port, np,
                                   h_net,  gid_net,  nn);
    hx_mlp_kernel<<<NB, 128>>>(Wc1, bc1, Wc2, bc2, Wc3, bc3, out);
}

// round 5
// speedup vs baseline: 3.5566x; 3.5566x over previous
#include <cuda_runtime.h>

// ---------------------------------------------------------------------------
// ClassifierHetero — live dataflow only (conv stack is dead code in reference):
//   hg[b] = [mean(h_comp|g=b), mean2(h_port|g=b), mean(h_net|g=b)]  -> [64,4]
//   out   = relu(relu(hg@Wc1+bc1)@Wc2+bc2)@Wc3+bc3                  -> [64,10]
//
// R3 changes vs R2:
//  - warp-aggregated segment sums (sorted gid -> uniform warps -> 1 shared
//    atomic per 32 elems instead of per elem; kills same-address ATOMS serial)
//  - no init kernel: accumulators are zero-init at load; the MLP kernel resets
//    each accumulator entry after consuming it (each entry has exactly one
//    consumer block), so the zero-invariant holds across graph replays.
// ---------------------------------------------------------------------------

#define NB 64  // number of graphs (B)

// Zero-initialized at module load; every kernel_launch invocation leaves them
// at zero again (mlp kernel consumes + resets). Deterministic across replays.
__device__ float g_sum[4 * NB];  // [0]=comp, [1]=port.x, [2]=port.y, [3]=net
__device__ int   g_cnt[3 * NB];  // [0]=comp, [1]=port,   [2]=net

// ---------------------------------------------------------------------------
// Reduce: warp-chunk segment sum. Each warp handles aligned 32-element windows
// of one node-type array; uniform-gid fast path does a shuffle reduction and a
// single shared atomic from lane 0.
// ---------------------------------------------------------------------------
__device__ __forceinline__ float warp_sum_f(float v) {
#pragma unroll
    for (int o = 16; o; o >>= 1) v += __shfl_xor_sync(0xffffffffu, v, o);
    return v;
}

__global__ void hx_reduce_kernel(const float* __restrict__ h_comp,
                                 const int*   __restrict__ gid_comp, int nc,
                                 const float* __restrict__ h_port,
                                 const int*   __restrict__ gid_port, int np,
                                 const float* __restrict__ h_net,
                                 const int*   __restrict__ gid_net,  int nn) {
    __shared__ float s_sum[4 * NB];
    __shared__ int   s_cnt[3 * NB];
    for (int i = threadIdx.x; i < 4 * NB; i += blockDim.x) s_sum[i] = 0.0f;
    for (int i = threadIdx.x; i < 3 * NB; i += blockDim.x) s_cnt[i] = 0;
    __syncthreads();

    const int lane   = threadIdx.x & 31;
    const int warp_g = (blockIdx.x * blockDim.x + threadIdx.x) >> 5;
    const int nwarps = (gridDim.x * blockDim.x) >> 5;

    const int wc_c = (nc + 31) >> 5;
    const int wc_p = (np + 31) >> 5;
    const int wc_n = (nn + 31) >> 5;
    const int wc_total = wc_c + wc_p + wc_n;

    for (int w = warp_g; w < wc_total; w += nwarps) {
        if (w < wc_c) {
            // ---- component: 1 column ----
            int idx = (w << 5) + lane;
            bool act = idx < nc;
            unsigned m = __ballot_sync(0xffffffffu, act);
            int   g = act ? gid_comp[idx] : -1;
            float v = act ? h_comp[idx]   : 0.0f;
            int g0 = __shfl_sync(0xffffffffu, g, 0);
            if (__all_sync(0xffffffffu, !act || g == g0)) {
                v = warp_sum_f(v);
                if (lane == 0) {
                    atomicAdd(&s_sum[0 * NB + g0], v);
                    atomicAdd(&s_cnt[0 * NB + g0], __popc(m));
                }
            } else if (act) {
                atomicAdd(&s_sum[0 * NB + g], v);
                atomicAdd(&s_cnt[0 * NB + g], 1);
            }
        } else if (w < wc_c + wc_p) {
            // ---- port: 2 columns (float2) ----
            int c = w - wc_c;
            int idx = (c << 5) + lane;
            bool act = idx < np;
            unsigned m = __ballot_sync(0xffffffffu, act);
            int g = act ? gid_port[idx] : -1;
            float2 v = act ? __ldg(reinterpret_cast<const float2*>(h_port) + idx)
                           : make_float2(0.0f, 0.0f);
            int g0 = __shfl_sync(0xffffffffu, g, 0);
            if (__all_sync(0xffffffffu, !act || g == g0)) {
                float sx = warp_sum_f(v.x);
                float sy = warp_sum_f(v.y);
                if (lane == 0) {
                    atomicAdd(&s_sum[1 * NB + g0], sx);
                    atomicAdd(&s_sum[2 * NB + g0], sy);
                    atomicAdd(&s_cnt[1 * NB + g0], __popc(m));
                }
            } else if (act) {
                atomicAdd(&s_sum[1 * NB + g], v.x);
                atomicAdd(&s_sum[2 * NB + g], v.y);
                atomicAdd(&s_cnt[1 * NB + g], 1);
            }
        } else {
            // ---- net: 1 column ----
            int c = w - wc_c - wc_p;
            int idx = (c << 5) + lane;
            bool act = idx < nn;
            unsigned m = __ballot_sync(0xffffffffu, act);
            int   g = act ? gid_net[idx] : -1;
            float v = act ? h_net[idx]   : 0.0f;
            int g0 = __shfl_sync(0xffffffffu, g, 0);
            if (__all_sync(0xffffffffu, !act || g == g0)) {
                v = warp_sum_f(v);
                if (lane == 0) {
                    atomicAdd(&s_sum[3 * NB + g0], v);
                    atomicAdd(&s_cnt[2 * NB + g0], __popc(m));
                }
            } else if (act) {
                atomicAdd(&s_sum[3 * NB + g], v);
                atomicAdd(&s_cnt[2 * NB + g], 1);
            }
        }
    }
    __syncthreads();

    // Sorted gids -> few nonzero bins per block; flush those only.
    for (int i = threadIdx.x; i < 4 * NB; i += blockDim.x)
        if (s_sum[i] != 0.0f) atomicAdd(&g_sum[i], s_sum[i]);
    for (int i = threadIdx.x; i < 3 * NB; i += blockDim.x)
        if (s_cnt[i] != 0) atomicAdd(&g_cnt[i], s_cnt[i]);
}

// ---------------------------------------------------------------------------
// MLP: one block per graph row. Consumes and RESETS its 7 accumulator entries
// (each entry has exactly one consumer block -> zero-invariant restored).
// ---------------------------------------------------------------------------
__global__ void hx_mlp_kernel(const float* __restrict__ Wc1, const float* __restrict__ bc1,
                              const float* __restrict__ Wc2, const float* __restrict__ bc2,
                              const float* __restrict__ Wc3, const float* __restrict__ bc3,
                              float* __restrict__ out) {
    const int b = blockIdx.x;
    const int j = threadIdx.x;  // 0..127

    __shared__ float s_raw[4];
    __shared__ float s_cntv[3];
    __shared__ float shg[4];
    __shared__ float sh1[128];
    __shared__ float sh2[128];

    if (j < 4) s_raw[j] = g_sum[j * NB + b];
    else if (j < 7) s_cntv[j - 4] = (float)g_cnt[(j - 4) * NB + b];
    __syncthreads();
    // Reset after all reads complete.
    if (j < 4) g_sum[j * NB + b] = 0.0f;
    else if (j < 7) g_cnt[(j - 4) * NB + b] = 0;

    if (j == 0) {
        shg[0] = s_raw[0] / fmaxf(s_cntv[0], 1.0f);
        shg[1] = s_raw[1] / fmaxf(s_cntv[1], 1.0f);
        shg[2] = s_raw[2] / fmaxf(s_cntv[1], 1.0f);
        shg[3] = s_raw[3] / fmaxf(s_cntv[2], 1.0f);
    }
    __syncthreads();

    const float hg0 = shg[0], hg1 = shg[1], hg2 = shg[2], hg3 = shg[3];

    float v = hg0 * Wc1[0 * 128 + j] + hg1 * Wc1[1 * 128 + j] +
              hg2 * Wc1[2 * 128 + j] + hg3 * Wc1[3 * 128 + j] + bc1[j];
    sh1[j] = fmaxf(v, 0.0f);
    __syncthreads();

    float acc = bc2[j];
#pragma unroll 8
    for (int k = 0; k < 128; k++) acc = fmaf(sh1[k], Wc2[k * 128 + j], acc);
    sh2[j] = fmaxf(acc, 0.0f);
    __syncthreads();

    if (j < 10) {
        float o = bc3[j];
#pragma unroll 8
        for (int k = 0; k < 128; k++) o = fmaf(sh2[k], Wc3[k * 10 + j], o);
        out[b * 10 + j] = o;
    }
}

extern "C" void kernel_launch(void* const* d_in, const int* in_sizes, int n_in,
                              void* d_out, int out_size) {
    // metadata order (reference signature order):
    //  0 h_comp  1 h_port  2 h_net | 3..6 edges (dead) | 7..9 gid_{comp,port,net}
    // 10..21 conv weights (dead) | 22 Wc1 23 bc1 24 Wc2 25 bc2 26 Wc3 27 bc3
    const float* h_comp  = (const float*)d_in[0];
    const float* h_port  = (const float*)d_in[1];
    const float* h_net   = (const float*)d_in[2];
    const int* gid_comp  = (const int*)d_in[7];
    const int* gid_port  = (const int*)d_in[8];
    const int* gid_net   = (const int*)d_in[9];
    const float* Wc1 = (const float*)d_in[22];
    const float* bc1 = (const float*)d_in[23];
    const float* Wc2 = (const float*)d_in[24];
    const float* bc2 = (const float*)d_in[25];
    const float* Wc3 = (const float*)d_in[26];
    const float* bc3 = (const float*)d_in[27];
    float* out = (float*)d_out;

    const int nc = in_sizes[0];
    const int np = in_sizes[1] / 2;
    const int nn = in_sizes[2];

    hx_reduce_kernel<<<592, 256>>>(h_comp, gid_comp, nc,
                                   h_port, gid_port, np,
                                   h_net,  gid_net,  nn);
    hx_mlp_kernel<<<NB, 128>>>(Wc1, bc1, Wc2, bc2, Wc3, bc3, out);
}

// round 7
// speedup vs baseline: 5.0238x; 1.4125x over previous
#include <cuda_runtime.h>

// ---------------------------------------------------------------------------
// ClassifierHetero — live dataflow only (conv stack is dead code in reference):
//   hg[b] = [mean(h_comp|g=b), mean2(h_port|g=b), mean(h_net|g=b)]  -> [64,4]
//   out   = relu(relu(hg@Wc1+bc1)@Wc2+bc2)@Wc3+bc3                  -> [64,10]
//
// R5 change vs R4: the MLP was latency-bound (regs=26 -> MLP~2 -> 64 serial
// DRAM round trips on Wc2). Full unroll + 4 accumulators + __launch_bounds__
// exposes 128 independent loads; latency amortized.
// ---------------------------------------------------------------------------

#define NB 64  // number of graphs (B)

// Zero at module load; MLP kernel consumes + resets each entry (exactly one
// consumer block per entry), so the zero-invariant holds across graph replays.
__device__ float g_sum[4 * NB];  // [0]=comp, [1]=port.x, [2]=port.y, [3]=net
__device__ int   g_cnt[3 * NB];  // [0]=comp, [1]=port,   [2]=net

__device__ __forceinline__ float warp_sum_f(float v) {
#pragma unroll
    for (int o = 16; o; o >>= 1) v += __shfl_xor_sync(0xffffffffu, v, o);
    return v;
}

__global__ void hx_reduce_kernel(const float* __restrict__ h_comp,
                                 const int*   __restrict__ gid_comp, int nc,
                                 const float* __restrict__ h_port,
                                 const int*   __restrict__ gid_port, int np,
                                 const float* __restrict__ h_net,
                                 const int*   __restrict__ gid_net,  int nn) {
    __shared__ float s_sum[4 * NB];
    __shared__ int   s_cnt[3 * NB];
    for (int i = threadIdx.x; i < 4 * NB; i += blockDim.x) s_sum[i] = 0.0f;
    for (int i = threadIdx.x; i < 3 * NB; i += blockDim.x) s_cnt[i] = 0;
    __syncthreads();

    const int lane   = threadIdx.x & 31;
    const int warp_g = (blockIdx.x * blockDim.x + threadIdx.x) >> 5;
    const int nwarps = (gridDim.x * blockDim.x) >> 5;

    const int wc_c = (nc + 31) >> 5;
    const int wc_p = (np + 31) >> 5;
    const int wc_n = (nn + 31) >> 5;
    const int wc_total = wc_c + wc_p + wc_n;

    for (int w = warp_g; w < wc_total; w += nwarps) {
        if (w < wc_c) {
            int idx = (w << 5) + lane;
            bool act = idx < nc;
            unsigned m = __ballot_sync(0xffffffffu, act);
            int   g = act ? gid_comp[idx] : -1;
            float v = act ? h_comp[idx]   : 0.0f;
            int g0 = __shfl_sync(0xffffffffu, g, 0);
            if (__all_sync(0xffffffffu, !act || g == g0)) {
                v = warp_sum_f(v);
                if (lane == 0) {
                    atomicAdd(&s_sum[0 * NB + g0], v);
                    atomicAdd(&s_cnt[0 * NB + g0], __popc(m));
                }
            } else if (act) {
                atomicAdd(&s_sum[0 * NB + g], v);
                atomicAdd(&s_cnt[0 * NB + g], 1);
            }
        } else if (w < wc_c + wc_p) {
            int c = w - wc_c;
            int idx = (c << 5) + lane;
            bool act = idx < np;
            unsigned m = __ballot_sync(0xffffffffu, act);
            int g = act ? gid_port[idx] : -1;
            float2 v = act ? __ldg(reinterpret_cast<const float2*>(h_port) + idx)
                           : make_float2(0.0f, 0.0f);
            int g0 = __shfl_sync(0xffffffffu, g, 0);
            if (__all_sync(0xffffffffu, !act || g == g0)) {
                float sx = warp_sum_f(v.x);
                float sy = warp_sum_f(v.y);
                if (lane == 0) {
                    atomicAdd(&s_sum[1 * NB + g0], sx);
                    atomicAdd(&s_sum[2 * NB + g0], sy);
                    atomicAdd(&s_cnt[1 * NB + g0], __popc(m));
                }
            } else if (act) {
                atomicAdd(&s_sum[1 * NB + g], v.x);
                atomicAdd(&s_sum[2 * NB + g], v.y);
                atomicAdd(&s_cnt[1 * NB + g], 1);
            }
        } else {
            int c = w - wc_c - wc_p;
            int idx = (c << 5) + lane;
            bool act = idx < nn;
            unsigned m = __ballot_sync(0xffffffffu, act);
            int   g = act ? gid_net[idx] : -1;
            float v = act ? h_net[idx]   : 0.0f;
            int g0 = __shfl_sync(0xffffffffu, g, 0);
            if (__all_sync(0xffffffffu, !act || g == g0)) {
                v = warp_sum_f(v);
                if (lane == 0) {
                    atomicAdd(&s_sum[3 * NB + g0], v);
                    atomicAdd(&s_cnt[2 * NB + g0], __popc(m));
                }
            } else if (act) {
                atomicAdd(&s_sum[3 * NB + g], v);
                atomicAdd(&s_cnt[2 * NB + g], 1);
            }
        }
    }
    __syncthreads();

    for (int i = threadIdx.x; i < 4 * NB; i += blockDim.x)
        if (s_sum[i] != 0.0f) atomicAdd(&g_sum[i], s_sum[i]);
    for (int i = threadIdx.x; i < 3 * NB; i += blockDim.x)
        if (s_cnt[i] != 0) atomicAdd(&g_cnt[i], s_cnt[i]);
}

// ---------------------------------------------------------------------------
// MLP: one block per graph row. Fully unrolled, multi-accumulator dot products
// so the 128 Wc2 loads per thread are issued independently (latency hidden).
// Consumes and RESETS its accumulator entries.
// ---------------------------------------------------------------------------
__global__ void __launch_bounds__(128, 1)
hx_mlp_kernel(const float* __restrict__ Wc1, const float* __restrict__ bc1,
              const float* __restrict__ Wc2, const float* __restrict__ bc2,
              const float* __restrict__ Wc3, const float* __restrict__ bc3,
              float* __restrict__ out) {
    const int b = blockIdx.x;
    const int j = threadIdx.x;  // 0..127

    __shared__ float s_raw[4];
    __shared__ float s_cntv[3];
    __shared__ float shg[4];
    __shared__ float sh1[128];
    __shared__ float sh2[128];

    // Issue bias load early (independent of everything below).
    const float bias2 = bc2[j];

    if (j < 4) s_raw[j] = g_sum[j * NB + b];
    else if (j < 7) s_cntv[j - 4] = (float)g_cnt[(j - 4) * NB + b];
    __syncthreads();
    if (j < 4) g_sum[j * NB + b] = 0.0f;       // reset after reads complete
    else if (j < 7) g_cnt[(j - 4) * NB + b] = 0;

    if (j == 0) {
        shg[0] = s_raw[0] / fmaxf(s_cntv[0], 1.0f);
        shg[1] = s_raw[1] / fmaxf(s_cntv[1], 1.0f);
        shg[2] = s_raw[2] / fmaxf(s_cntv[1], 1.0f);
        shg[3] = s_raw[3] / fmaxf(s_cntv[2], 1.0f);
    }
    __syncthreads();

    const float hg0 = shg[0], hg1 = shg[1], hg2 = shg[2], hg3 = shg[3];

    float v = hg0 * Wc1[0 * 128 + j] + hg1 * Wc1[1 * 128 + j] +
              hg2 * Wc1[2 * 128 + j] + hg3 * Wc1[3 * 128 + j] + bc1[j];
    sh1[j] = fmaxf(v, 0.0f);
    __syncthreads();

    // ---- h2 = relu(sh1 @ Wc2 + bc2): 128 independent coalesced loads ----
    const float* __restrict__ w2 = Wc2 + j;
    float a0 = 0.0f, a1 = 0.0f, a2 = 0.0f, a3 = 0.0f;
#pragma unroll
    for (int k = 0; k < 128; k += 4) {
        a0 = fmaf(sh1[k + 0], w2[(k + 0) * 128], a0);
        a1 = fmaf(sh1[k + 1], w2[(k + 1) * 128], a1);
        a2 = fmaf(sh1[k + 2], w2[(k + 2) * 128], a2);
        a3 = fmaf(sh1[k + 3], w2[(k + 3) * 128], a3);
    }
    sh2[j] = fmaxf((a0 + a1) + (a2 + a3) + bias2, 0.0f);
    __syncthreads();

    // ---- out = sh2 @ Wc3 + bc3: full unroll, 4 accumulators ----
    if (j < 10) {
        const float* __restrict__ w3 = Wc3 + j;
        float o0 = 0.0f, o1 = 0.0f, o2 = 0.0f, o3 = 0.0f;
#pragma unroll
        for (int k = 0; k < 128; k += 4) {
            o0 = fmaf(sh2[k + 0], w3[(k + 0) * 10], o0);
            o1 = fmaf(sh2[k + 1], w3[(k + 1) * 10], o1);
            o2 = fmaf(sh2[k + 2], w3[(k + 2) * 10], o2);
            o3 = fmaf(sh2[k + 3], w3[(k + 3) * 10], o3);
        }
        out[b * 10 + j] = (o0 + o1) + (o2 + o3) + bc3[j];
    }
}

extern "C" void kernel_launch(void* const* d_in, const int* in_sizes, int n_in,
                              void* d_out, int out_size) {
    // metadata order: 0 h_comp  1 h_port  2 h_net | 3..6 edges (dead)
    // 7..9 gid_{comp,port,net} | 10..21 conv weights (dead)
    // 22 Wc1 23 bc1 24 Wc2 25 bc2 26 Wc3 27 bc3
    const float* h_comp  = (const float*)d_in[0];
    const float* h_port  = (const float*)d_in[1];
    const float* h_net   = (const float*)d_in[2];
    const int* gid_comp  = (const int*)d_in[7];
    const int* gid_port  = (const int*)d_in[8];
    const int* gid_net   = (const int*)d_in[9];
    const float* Wc1 = (const float*)d_in[22];
    const float* bc1 = (const float*)d_in[23];
    const float* Wc2 = (const float*)d_in[24];
    const float* bc2 = (const float*)d_in[25];
    const float* Wc3 = (const float*)d_in[26];
    const float* bc3 = (const float*)d_in[27];
    float* out = (float*)d_out;

    const int nc = in_sizes[0];
    const int np = in_sizes[1] / 2;
    const int nn = in_sizes[2];

    hx_reduce_kernel<<<592, 256>>>(h_comp, gid_comp, nc,
                                   h_port, gid_port, np,
                                   h_net,  gid_net,  nn);
    hx_mlp_kernel<<<NB, 128>>>(Wc1, bc1, Wc2, bc2, Wc3, bc3, out);
}